// round 5
// baseline (speedup 1.0000x reference)
#include <cuda_runtime.h>
#include <cstdint>

// Problem constants (fixed by the dataset)
#define BATCH 2
#define CH    128
#define DW    64
#define DL    64
#define DH    64
#define SPAT  (DW*DL*DH)          // 262144
#define OUTW  7
#define OUTL  7
#define OUTH  7
#define NBINS (OUTW*OUTL*OUTH)    // 343

// Scratch: input transposed to (B, W, L, H, C) so channels are contiguous.
// 2 * 262144 * 128 floats = 256 MB static device array (allowed scratch).
__device__ float g_vol[(size_t)BATCH * SPAT * CH];

// ---------------------------------------------------------------------------
// Kernel 1: transpose (B, C, S) -> (B, S, C), S = W*L*H.
// Classic 32x32 shared-memory tile, 32x8 threads.
// ---------------------------------------------------------------------------
__global__ void transpose_kernel(const float* __restrict__ in)
{
    __shared__ float tile[32][33];

    const int b  = blockIdx.z;
    const int tx = threadIdx.x;
    const int ty = threadIdx.y;

    // load: rows = channel (C=128), cols = spatial (S)
    {
        const int s = blockIdx.x * 32 + tx;
        #pragma unroll
        for (int j = 0; j < 4; ++j) {
            const int c = blockIdx.y * 32 + ty + j * 8;
            tile[ty + j * 8][tx] = in[((size_t)(b * CH + c)) * SPAT + s];
        }
    }
    __syncthreads();
    // store: rows = spatial, cols = channel
    {
        const int c = blockIdx.y * 32 + tx;
        #pragma unroll
        for (int j = 0; j < 4; ++j) {
            const int s = blockIdx.x * 32 + ty + j * 8;
            g_vol[((size_t)b * SPAT + s) * CH + c] = tile[tx][ty + j * 8];
        }
    }
}

// ---------------------------------------------------------------------------
// Kernel 2: ROI-align rotated 3D gather.
// One warp per (roi, bin). Lane = float4 channel slice (32 lanes * 4 = 128 ch).
// Each warp: 8 samples (2x2x2 within bin) x 8 trilinear corners, coalesced
// 512B loads from the channel-contiguous volume.
// ---------------------------------------------------------------------------
__global__ void __launch_bounds__(256)
roi_gather_kernel(const float* __restrict__ rois,
                  const float* __restrict__ scale_p,
                  float* __restrict__ out,
                  int N)
{
    const int warp = threadIdx.x >> 5;
    const int lane = threadIdx.x & 31;
    const int bin  = blockIdx.x * 8 + warp;
    const int n    = blockIdx.y;
    if (bin >= NBINS) return;

    const float scale = *scale_p;
    const float* r = rois + (size_t)n * 8;
    const int   b  = (int)r[0];
    const float cx = r[1] * scale;
    const float cy = r[2] * scale;
    const float cz = r[3] * scale;
    const float sx = r[4] * scale;
    const float sy = r[5] * scale;
    const float sz = r[6] * scale;
    const float th = r[7];
    const float ct = cosf(th);
    const float st = sinf(th);

    // step = (size/nbins)/SR, matching reference arithmetic order
    const float stepx = (sx / 7.0f) * 0.5f;
    const float stepy = (sy / 7.0f) * 0.5f;
    const float stepz = (sz / 7.0f) * 0.5f;

    const int ow  = bin / 49;
    const int rem = bin % 49;
    const int ol  = rem / 7;
    const int oh  = rem % 7;

    // float4 view of the volume, offset by this lane's channel slice
    const float4* __restrict__ vol4 =
        reinterpret_cast<const float4*>(g_vol) + (size_t)b * SPAT * 32 + lane;

    float4 acc = make_float4(0.f, 0.f, 0.f, 0.f);

    #pragma unroll
    for (int jx = 0; jx < 2; ++jx) {
        const int ix = ow * 2 + jx;
        const float fx = -sx * 0.5f + ((float)ix + 0.5f) * stepx;
        #pragma unroll
        for (int jy = 0; jy < 2; ++jy) {
            const int iy = ol * 2 + jy;
            const float fy = -sy * 0.5f + ((float)iy + 0.5f) * stepy;
            const float xs = ct * fx - st * fy + cx;
            const float ys = st * fx + ct * fy + cy;
            #pragma unroll
            for (int jz = 0; jz < 2; ++jz) {
                const int iz = oh * 2 + jz;
                const float zs = (-sz * 0.5f + ((float)iz + 0.5f) * stepz) + cz;

                const bool valid = (xs > -1.0f) && (xs < (float)DW) &&
                                   (ys > -1.0f) && (ys < (float)DL) &&
                                   (zs > -1.0f) && (zs < (float)DH);
                if (!valid) continue;

                const float xc = fminf(fmaxf(xs, 0.f), (float)(DW - 1));
                const float yc = fminf(fmaxf(ys, 0.f), (float)(DL - 1));
                const float zc = fminf(fmaxf(zs, 0.f), (float)(DH - 1));

                const int x0 = (int)floorf(xc);
                const int y0 = (int)floorf(yc);
                const int z0 = (int)floorf(zc);
                const int dx = (x0 + 1 <= DW - 1) ? 1 : 0;
                const int dy = (y0 + 1 <= DL - 1) ? 1 : 0;
                const int dz = (z0 + 1 <= DH - 1) ? 1 : 0;

                const float lx = xc - (float)x0, hx = 1.f - lx;
                const float ly = yc - (float)y0, hy = 1.f - ly;
                const float lz = zc - (float)z0, hz = 1.f - lz;

                // spatial index (within batch): x*4096 + y*64 + z
                const int s000 = (x0 * DL + y0) * DH + z0;
                const int sx1  = dx * (DL * DH);
                const int sy1  = dy * DH;
                const int sz1  = dz;

                const float4 v000 = vol4[(size_t)(s000)               * 32];
                const float4 v001 = vol4[(size_t)(s000 + sz1)         * 32];
                const float4 v010 = vol4[(size_t)(s000 + sy1)         * 32];
                const float4 v011 = vol4[(size_t)(s000 + sy1 + sz1)   * 32];
                const float4 v100 = vol4[(size_t)(s000 + sx1)         * 32];
                const float4 v101 = vol4[(size_t)(s000 + sx1 + sz1)   * 32];
                const float4 v110 = vol4[(size_t)(s000 + sx1 + sy1)   * 32];
                const float4 v111 = vol4[(size_t)(s000 + sx1 + sy1 + sz1) * 32];

                const float w000 = hx * hy * hz;
                const float w001 = hx * hy * lz;
                const float w010 = hx * ly * hz;
                const float w011 = hx * ly * lz;
                const float w100 = lx * hy * hz;
                const float w101 = lx * hy * lz;
                const float w110 = lx * ly * hz;
                const float w111 = lx * ly * lz;

                acc.x += w000*v000.x + w001*v001.x + w010*v010.x + w011*v011.x
                       + w100*v100.x + w101*v101.x + w110*v110.x + w111*v111.x;
                acc.y += w000*v000.y + w001*v001.y + w010*v010.y + w011*v011.y
                       + w100*v100.y + w101*v101.y + w110*v110.y + w111*v111.y;
                acc.z += w000*v000.z + w001*v001.z + w010*v010.z + w011*v011.z
                       + w100*v100.z + w101*v101.z + w110*v110.z + w111*v111.z;
                acc.w += w000*v000.w + w001*v001.w + w010*v010.w + w011*v011.w
                       + w100*v100.w + w101*v101.w + w110*v110.w + w111*v111.w;
            }
        }
    }

    acc.x *= 0.125f; acc.y *= 0.125f; acc.z *= 0.125f; acc.w *= 0.125f;

    // out layout: (N, C, 7,7,7). lane owns channels [lane*4, lane*4+4)
    float* o = out + ((size_t)n * CH + (size_t)lane * 4) * NBINS + bin;
    o[0 * NBINS] = acc.x;
    o[1 * NBINS] = acc.y;
    o[2 * NBINS] = acc.z;
    o[3 * NBINS] = acc.w;
}

extern "C" void kernel_launch(void* const* d_in, const int* in_sizes, int n_in,
                              void* d_out, int out_size)
{
    const float* input  = (const float*)d_in[0];
    const float* rois   = (const float*)d_in[1];
    const float* scale  = (const float*)d_in[2];
    float* out = (float*)d_out;
    const int N = in_sizes[1] / 8;

    {
        dim3 grid(SPAT / 32, CH / 32, BATCH);   // (8192, 4, 2)
        dim3 block(32, 8);
        transpose_kernel<<<grid, block>>>(input);
    }
    {
        dim3 grid((NBINS + 7) / 8, N);          // (43, 128)
        dim3 block(256);
        roi_gather_kernel<<<grid, block>>>(rois, scale, out, N);
    }
}

// round 10
// speedup vs baseline: 1.3338x; 1.3338x over previous
#include <cuda_runtime.h>
#include <cuda_fp16.h>
#include <cstdint>

// Problem constants (fixed by the dataset)
#define BATCH 2
#define CH    128
#define DW    64
#define DL    64
#define DH    64
#define SPAT  (DW*DL*DH)          // 262144
#define OUTW  7
#define OUTL  7
#define OUTH  7
#define NBINS (OUTW*OUTL*OUTH)    // 343

// Scratch: input transposed to (B, W, L, H, C) in fp16 so channels are
// contiguous. 2 * 262144 * 128 halves = 128 MB static device array.
__device__ __half g_vol[(size_t)BATCH * SPAT * CH];

struct alignas(8) H4 { __half2 a, b; };

// ---------------------------------------------------------------------------
// Kernel 1: transpose (B, C, S) fp32 -> (B, S, C) fp16, S = W*L*H.
// 32x32 tile, 256 threads. float4 global loads, 8-byte half4 global stores.
// ---------------------------------------------------------------------------
__global__ void __launch_bounds__(256)
transpose_half_kernel(const float* __restrict__ in)
{
    __shared__ float tile[32][33];

    const int b  = blockIdx.z;
    const int t  = threadIdx.x;
    const int s0 = blockIdx.x * 32;
    const int c0 = blockIdx.y * 32;

    // Phase 1: load float4 along spatial (contiguous). rows=channel.
    {
        const int c_local = t >> 3;          // 0..31
        const int s4      = t & 7;           // 0..7  (x4 spatial)
        const float4 v = *reinterpret_cast<const float4*>(
            in + ((size_t)(b * CH + c0 + c_local)) * SPAT + s0 + s4 * 4);
        tile[s4 * 4 + 0][c_local] = v.x;     // banks (4*s4+i + c_local)%32: conflict-free
        tile[s4 * 4 + 1][c_local] = v.y;
        tile[s4 * 4 + 2][c_local] = v.z;
        tile[s4 * 4 + 3][c_local] = v.w;
    }
    __syncthreads();
    // Phase 2: write 4 consecutive channels as one 8-byte half4 store.
    {
        const int s_local = t >> 3;          // 0..31
        const int c4      = t & 7;           // 0..7  (x4 channels)
        H4 h;
        h.a = __floats2half2_rn(tile[s_local][c4 * 4 + 0], tile[s_local][c4 * 4 + 1]);
        h.b = __floats2half2_rn(tile[s_local][c4 * 4 + 2], tile[s_local][c4 * 4 + 3]);
        *reinterpret_cast<H4*>(
            g_vol + ((size_t)b * SPAT + s0 + s_local) * CH + c0 + c4 * 4) = h;
    }
}

// ---------------------------------------------------------------------------
// Kernel 2: ROI-align rotated 3D gather from the fp16 channel-contiguous
// volume. One warp per (roi, bin); lane owns 4 channels (one uint2 / 8B).
// Output staged through smem so global writes are bin-contiguous.
// ---------------------------------------------------------------------------
__device__ __forceinline__ void fma_corner(float4& acc, uint2 u, float w)
{
    const float2 lo = __half22float2(*reinterpret_cast<const __half2*>(&u.x));
    const float2 hi = __half22float2(*reinterpret_cast<const __half2*>(&u.y));
    acc.x += w * lo.x; acc.y += w * lo.y;
    acc.z += w * hi.x; acc.w += w * hi.y;
}

__global__ void __launch_bounds__(256)
roi_gather_kernel(const float* __restrict__ rois,
                  const float* __restrict__ scale_p,
                  float* __restrict__ out,
                  int N)
{
    // 8 bins x 128 channels staging. float4 rows padded to 33 -> scalar reads
    // at pitch 132 floats are bank-conflict-free.
    __shared__ float4 s_out4[8][33];

    const int warp = threadIdx.x >> 5;
    const int lane = threadIdx.x & 31;
    const int bin  = blockIdx.x * 8 + warp;
    const int n    = blockIdx.y;

    float4 acc = make_float4(0.f, 0.f, 0.f, 0.f);

    if (bin < NBINS) {
        const float scale = *scale_p;
        const float* r = rois + (size_t)n * 8;
        const int   b  = (int)r[0];
        const float cx = r[1] * scale;
        const float cy = r[2] * scale;
        const float cz = r[3] * scale;
        const float sx = r[4] * scale;
        const float sy = r[5] * scale;
        const float sz = r[6] * scale;
        const float th = r[7];
        const float ct = cosf(th);
        const float st = sinf(th);

        // step = (size/nbins)/SR, matching reference arithmetic order
        const float stepx = (sx / 7.0f) * 0.5f;
        const float stepy = (sy / 7.0f) * 0.5f;
        const float stepz = (sz / 7.0f) * 0.5f;

        const int ow  = bin / 49;
        const int rem = bin % 49;
        const int ol  = rem / 7;
        const int oh  = rem % 7;

        // uint2 view (4 halves = this lane's channel slice)
        const uint2* __restrict__ vol2 =
            reinterpret_cast<const uint2*>(g_vol) + (size_t)b * SPAT * 32 + lane;

        #pragma unroll
        for (int jx = 0; jx < 2; ++jx) {
            const int ix = ow * 2 + jx;
            const float fx = -sx * 0.5f + ((float)ix + 0.5f) * stepx;
            #pragma unroll
            for (int jy = 0; jy < 2; ++jy) {
                const int iy = ol * 2 + jy;
                const float fy = -sy * 0.5f + ((float)iy + 0.5f) * stepy;
                const float xs = ct * fx - st * fy + cx;
                const float ys = st * fx + ct * fy + cy;
                #pragma unroll
                for (int jz = 0; jz < 2; ++jz) {
                    const int iz = oh * 2 + jz;
                    const float zs = (-sz * 0.5f + ((float)iz + 0.5f) * stepz) + cz;

                    const bool valid = (xs > -1.0f) && (xs < (float)DW) &&
                                       (ys > -1.0f) && (ys < (float)DL) &&
                                       (zs > -1.0f) && (zs < (float)DH);
                    if (!valid) continue;

                    const float xc = fminf(fmaxf(xs, 0.f), (float)(DW - 1));
                    const float yc = fminf(fmaxf(ys, 0.f), (float)(DL - 1));
                    const float zc = fminf(fmaxf(zs, 0.f), (float)(DH - 1));

                    const int x0 = (int)floorf(xc);
                    const int y0 = (int)floorf(yc);
                    const int z0 = (int)floorf(zc);
                    const int dx = (x0 + 1 <= DW - 1) ? 1 : 0;
                    const int dy = (y0 + 1 <= DL - 1) ? 1 : 0;
                    const int dz = (z0 + 1 <= DH - 1) ? 1 : 0;

                    const float lx = xc - (float)x0, hx = 1.f - lx;
                    const float ly = yc - (float)y0, hy = 1.f - ly;
                    const float lz = zc - (float)z0, hz = 1.f - lz;

                    const int s000 = (x0 * DL + y0) * DH + z0;
                    const int sx1  = dx * (DL * DH);
                    const int sy1  = dy * DH;
                    const int sz1  = dz;

                    // batch the 8 loads for MLP
                    const uint2 v000 = vol2[(size_t)(s000)                   * 32];
                    const uint2 v001 = vol2[(size_t)(s000 + sz1)             * 32];
                    const uint2 v010 = vol2[(size_t)(s000 + sy1)             * 32];
                    const uint2 v011 = vol2[(size_t)(s000 + sy1 + sz1)       * 32];
                    const uint2 v100 = vol2[(size_t)(s000 + sx1)             * 32];
                    const uint2 v101 = vol2[(size_t)(s000 + sx1 + sz1)       * 32];
                    const uint2 v110 = vol2[(size_t)(s000 + sx1 + sy1)       * 32];
                    const uint2 v111 = vol2[(size_t)(s000 + sx1 + sy1 + sz1) * 32];

                    fma_corner(acc, v000, hx * hy * hz);
                    fma_corner(acc, v001, hx * hy * lz);
                    fma_corner(acc, v010, hx * ly * hz);
                    fma_corner(acc, v011, hx * ly * lz);
                    fma_corner(acc, v100, lx * hy * hz);
                    fma_corner(acc, v101, lx * hy * lz);
                    fma_corner(acc, v110, lx * ly * hz);
                    fma_corner(acc, v111, lx * ly * lz);
                }
            }
        }
        acc.x *= 0.125f; acc.y *= 0.125f; acc.z *= 0.125f; acc.w *= 0.125f;
    }

    // Stage: warp=bin row, lane=4-channel float4. STS.128, warp-contiguous.
    s_out4[warp][lane] = acc;
    __syncthreads();

    // Write: bins contiguous in gmem (out[n][c][bin]). Each group of 8 lanes
    // writes 8 consecutive bins for one channel -> full 32B sectors.
    {
        const float* s_outf = reinterpret_cast<const float*>(s_out4);
        const int bin_local = threadIdx.x & 7;
        const int bin_g     = blockIdx.x * 8 + bin_local;
        if (bin_g < NBINS) {
            const int cbase = threadIdx.x >> 3;   // 0..31
            #pragma unroll
            for (int k = 0; k < 4; ++k) {
                const int c = cbase + 32 * k;
                out[((size_t)n * CH + c) * NBINS + bin_g] =
                    s_outf[bin_local * 132 + c];
            }
        }
    }
}

extern "C" void kernel_launch(void* const* d_in, const int* in_sizes, int n_in,
                              void* d_out, int out_size)
{
    const float* input  = (const float*)d_in[0];
    const float* rois   = (const float*)d_in[1];
    const float* scale  = (const float*)d_in[2];
    float* out = (float*)d_out;
    const int N = in_sizes[1] / 8;

    {
        dim3 grid(SPAT / 32, CH / 32, BATCH);   // (8192, 4, 2)
        transpose_half_kernel<<<grid, 256>>>(input);
    }
    {
        dim3 grid((NBINS + 7) / 8, N);          // (43, 128)
        roi_gather_kernel<<<grid, 256>>>(rois, scale, out, N);
    }
}